// round 6
// baseline (speedup 1.0000x reference)
#include <cuda_runtime.h>
#include <stdint.h>

#define NTHREADS 256

__device__ __forceinline__ float silu_fast(float x) {
    // x * sigmoid(x) via MUFU.EX2 + MUFU.RCP.
    return __fdividef(x, 1.0f + __expf(-x));
}

// Float-domain quantize: round-half-even then clamp. ±127 are exact floats and
// rint is monotone, so this equals clip(round(a/scale), -127, 127).
__device__ __forceinline__ float quantf(float a, float inv_scale) {
    return fminf(fmaxf(rintf(a * inv_scale), -127.0f), 127.0f);
}

__device__ __forceinline__ int quanti(float a, float inv_scale) {
    int q = __float2int_rn(a * inv_scale);
    return max(-127, min(127, q));
}

// Persistent grid-stride kernel. One token per CTA-iteration, 256 threads,
// d == 4*NTHREADS*D4PER, act held in registers, one __syncthreads per token
// (wmax parity double-buffered so no second barrier is needed).
template <int D4PER, bool OUT_FLOAT>
__global__ __launch_bounds__(NTHREADS, 6)
void swiglu_quant_persist(const float* __restrict__ input,
                          const float* __restrict__ smooth_scale,
                          const int*   __restrict__ sorted_ids,
                          const int*   __restrict__ topk,
                          void*        __restrict__ qout,
                          float*       __restrict__ qscale,
                          int d, int N)
{
    const int t = threadIdx.x;
    __shared__ float wmax[2][NTHREADS / 32];

    int token = blockIdx.x;
    if (token >= N) return;

    // Prefetch ids for the first token.
    int sid = __ldg(sorted_ids + token);
    int e   = __ldg(topk + token);

    int parity = 0;
    for (; token < N; token += gridDim.x, parity ^= 1) {
        const float4* gate = reinterpret_cast<const float4*>(input + (size_t)sid * (size_t)(2 * d));
        const float4* up   = gate + (d >> 2);
        const float4* ss   = reinterpret_cast<const float4*>(smooth_scale + (size_t)e * (size_t)d);

        float4 act[D4PER];
        float amax = 0.0f;

        #pragma unroll
        for (int k = 0; k < D4PER; k++) {
            const int i = t + k * NTHREADS;
            const float4 g = __ldg(gate + i);
            const float4 u = __ldg(up + i);
            const float4 s = __ldg(ss + i);   // L1-resident across iterations (64KB table)
            float4 a;
            a.x = silu_fast(g.x) * u.x * s.x;
            a.y = silu_fast(g.y) * u.y * s.y;
            a.z = silu_fast(g.z) * u.z * s.z;
            a.w = silu_fast(g.w) * u.w * s.w;
            act[k] = a;
            amax = fmaxf(amax, fmaxf(fmaxf(fabsf(a.x), fabsf(a.y)),
                                     fmaxf(fabsf(a.z), fabsf(a.w))));
        }

        // Prefetch next token's ids before the barrier so the next gather's
        // address chain is ready as soon as stores issue.
        const int next = token + gridDim.x;
        if (next < N) {
            sid = __ldg(sorted_ids + next);
            e   = __ldg(topk + next);
        }

        // Block amax: warp shuffle reduce, then every thread scans the warp maxima.
        #pragma unroll
        for (int o = 16; o > 0; o >>= 1)
            amax = fmaxf(amax, __shfl_xor_sync(0xffffffffu, amax, o));
        if ((t & 31) == 0) wmax[parity][t >> 5] = amax;
        __syncthreads();
        float bmax = wmax[parity][0];
        #pragma unroll
        for (int w = 1; w < NTHREADS / 32; w++) bmax = fmaxf(bmax, wmax[parity][w]);

        // Emitted scale matches the reference exactly (IEEE divide).
        const float scale     = (bmax > 0.0f) ? __fdiv_rn(bmax, 127.0f) : 1.0f;
        const float inv_scale = (bmax > 0.0f) ? __fdividef(127.0f, bmax) : 1.0f;
        if (t == 0) qscale[token] = scale;

        if (OUT_FLOAT) {
            float4* orow = reinterpret_cast<float4*>((float*)qout + (size_t)token * (size_t)d);
            #pragma unroll
            for (int k = 0; k < D4PER; k++) {
                const int i = t + k * NTHREADS;
                const float4 a = act[k];
                float4 f;
                f.x = quantf(a.x, inv_scale);
                f.y = quantf(a.y, inv_scale);
                f.z = quantf(a.z, inv_scale);
                f.w = quantf(a.w, inv_scale);
                __stcs(orow + i, f);   // streaming store: output is never re-read
            }
        } else {
            char4* orow = reinterpret_cast<char4*>((int8_t*)qout + (size_t)token * (size_t)d);
            #pragma unroll
            for (int k = 0; k < D4PER; k++) {
                const int i = t + k * NTHREADS;
                const float4 a = act[k];
                char4 c;
                c.x = (char)quanti(a.x, inv_scale);
                c.y = (char)quanti(a.y, inv_scale);
                c.z = (char)quanti(a.z, inv_scale);
                c.w = (char)quanti(a.w, inv_scale);
                orow[i] = c;
            }
        }
    }
}

// Generic fallback for any d (smem-staged act), one CTA per token.
template <bool OUT_FLOAT>
__global__ __launch_bounds__(NTHREADS, 1)
void swiglu_quant_generic(const float* __restrict__ input,
                          const float* __restrict__ smooth_scale,
                          const int*   __restrict__ sorted_ids,
                          const int*   __restrict__ topk,
                          void*        __restrict__ qout,
                          float*       __restrict__ qscale,
                          int d)
{
    extern __shared__ float s_act[];
    const int token = blockIdx.x;
    const int t     = threadIdx.x;

    const int sid = __ldg(sorted_ids + token);
    const int e   = __ldg(topk + token);

    const float* gate = input + (size_t)sid * (size_t)(2 * d);
    const float* up   = gate + d;
    const float* ss   = smooth_scale + (size_t)e * (size_t)d;

    float amax = 0.0f;
    for (int j = t; j < d; j += NTHREADS) {
        float a = silu_fast(__ldg(gate + j)) * __ldg(up + j) * __ldg(ss + j);
        s_act[j] = a;
        amax = fmaxf(amax, fabsf(a));
    }

    __shared__ float wmax[NTHREADS / 32];
    #pragma unroll
    for (int o = 16; o > 0; o >>= 1)
        amax = fmaxf(amax, __shfl_xor_sync(0xffffffffu, amax, o));
    if ((t & 31) == 0) wmax[t >> 5] = amax;
    __syncthreads();
    float bmax = wmax[0];
    #pragma unroll
    for (int w = 1; w < NTHREADS / 32; w++) bmax = fmaxf(bmax, wmax[w]);

    const float scale     = (bmax > 0.0f) ? __fdiv_rn(bmax, 127.0f) : 1.0f;
    const float inv_scale = (bmax > 0.0f) ? __fdividef(127.0f, bmax) : 1.0f;
    if (t == 0) qscale[token] = scale;

    if (OUT_FLOAT) {
        float* orow = (float*)qout + (size_t)token * (size_t)d;
        for (int j = t; j < d; j += NTHREADS)
            orow[j] = quantf(s_act[j], inv_scale);
    } else {
        int8_t* orow = (int8_t*)qout + (size_t)token * (size_t)d;
        for (int j = t; j < d; j += NTHREADS)
            orow[j] = (int8_t)quanti(s_act[j], inv_scale);
    }
}

extern "C" void kernel_launch(void* const* d_in, const int* in_sizes, int n_in,
                              void* d_out, int out_size)
{
    const float* input        = (const float*)d_in[0];
    const float* smooth_scale = (const float*)d_in[1];
    const int*   sorted_ids   = (const int*)d_in[2];
    const int*   topk         = (const int*)d_in[3];

    const int N   = in_sizes[2];             // number of tokens (16384)
    const int fc1 = in_sizes[0] / N;         // 4096
    const int d   = fc1 / 2;                 // 2048

    // Output packing (f32 common dtype confirmed in R3/R4):
    const long long want_f32 = (long long)N * d + N;
    const bool out_float = ((long long)out_size == want_f32);

    void*  qout   = d_out;
    float* qscale = out_float
        ? ((float*)d_out + (size_t)N * (size_t)d)
        : (float*)((int8_t*)d_out + (size_t)N * (size_t)d);

    // Persistent grid: 6 CTAs per SM (matches __launch_bounds__(256, 6)).
    int sms = 148;
    cudaDeviceGetAttribute(&sms, cudaDevAttrMultiProcessorCount, 0);
    int grid = sms * 6;
    if (grid > N) grid = N;

    const int per = d / (4 * NTHREADS);      // float4s per thread per half (2 for d=2048)
    const bool fast = (d % (4 * NTHREADS) == 0) && per >= 1 && per <= 4;

    if (fast) {
        if (out_float) {
            switch (per) {
                case 1: swiglu_quant_persist<1, true><<<grid, NTHREADS>>>(input, smooth_scale, sorted_ids, topk, qout, qscale, d, N); break;
                case 2: swiglu_quant_persist<2, true><<<grid, NTHREADS>>>(input, smooth_scale, sorted_ids, topk, qout, qscale, d, N); break;
                case 3: swiglu_quant_persist<3, true><<<grid, NTHREADS>>>(input, smooth_scale, sorted_ids, topk, qout, qscale, d, N); break;
                default: swiglu_quant_persist<4, true><<<grid, NTHREADS>>>(input, smooth_scale, sorted_ids, topk, qout, qscale, d, N); break;
            }
        } else {
            switch (per) {
                case 1: swiglu_quant_persist<1, false><<<grid, NTHREADS>>>(input, smooth_scale, sorted_ids, topk, qout, qscale, d, N); break;
                case 2: swiglu_quant_persist<2, false><<<grid, NTHREADS>>>(input, smooth_scale, sorted_ids, topk, qout, qscale, d, N); break;
                case 3: swiglu_quant_persist<3, false><<<grid, NTHREADS>>>(input, smooth_scale, sorted_ids, topk, qout, qscale, d, N); break;
                default: swiglu_quant_persist<4, false><<<grid, NTHREADS>>>(input, smooth_scale, sorted_ids, topk, qout, qscale, d, N); break;
            }
        }
    } else {
        if (out_float)
            swiglu_quant_generic<true><<<N, NTHREADS, d * sizeof(float)>>>(input, smooth_scale, sorted_ids, topk, qout, qscale, d);
        else
            swiglu_quant_generic<false><<<N, NTHREADS, d * sizeof(float)>>>(input, smooth_scale, sorted_ids, topk, qout, qscale, d);
    }
}